// round 12
// baseline (speedup 1.0000x reference)
#include <cuda_runtime.h>
#include <math.h>

#define B_ 8
#define C_ 256
#define T_ 2048
#define DEPTH_ 256
#define OCH 384
#define SSTR 322                /* even -> 8B-aligned paired loads */
#define SS_F (64*SSTR)          /* 20608 floats */
#define AUX_F 6144              /* QK: Qp 4096 + Kt 2048 | PV: Vs 4096 + Pd 2048 */
#define SM_F (SS_F + AUX_F)     /* 26752 floats = 107008 B -> 2 CTA/SM */

typedef unsigned long long u64t;

__device__ float g_Wt[C_*OCH];
__device__ float g_bf[OCH];
__device__ float g_qkv[B_*T_*OCH];   // [b][t][384]: q|k|v
__device__ float g_qkT[B_*128*T_];   // [b][o][t]: o<64 q*0.125, o>=64 k
__device__ float g_denom[T_];

static __device__ __forceinline__ u64t pk2(float a,float b){u64t r;asm("mov.b64 %0,{%1,%2};":"=l"(r):"f"(a),"f"(b));return r;}
static __device__ __forceinline__ u64t dup2(float a){return pk2(a,a);}
static __device__ __forceinline__ void fma2(u64t&d,u64t a,u64t b){asm("fma.rn.f32x2 %0,%1,%2,%3;":"=l"(d):"l"(a),"l"(b),"l"(d));}
static __device__ __forceinline__ void unpk(u64t v,float&x,float&y){asm("mov.b64 {%0,%1},%2;":"=f"(x),"=f"(y):"l"(v));}
static __device__ __forceinline__ unsigned smem_u32(const void* p){
    unsigned a; asm("{ .reg .u64 t; cvta.to.shared.u64 t, %1; cvt.u32.u64 %0, t; }":"=r"(a):"l"(p)); return a;
}
static __device__ __forceinline__ void cpa16(unsigned dst, const void* src){
    asm volatile("cp.async.cg.shared.global [%0], [%1], 16;" :: "r"(dst), "l"(src));
}
#define CPCOMMIT asm volatile("cp.async.commit_group;" ::: "memory")
#define CPWAIT0  asm volatile("cp.async.wait_group 0;" ::: "memory")

// ---------------------------------------------------------------------------
__global__ void fold_k(
    const float* __restrict__ kW,const float* __restrict__ kb,const float* __restrict__ kg,
    const float* __restrict__ kbe,const float* __restrict__ kmu,const float* __restrict__ kva,
    const float* __restrict__ qW,const float* __restrict__ qb,const float* __restrict__ qg,
    const float* __restrict__ qbe,const float* __restrict__ qmu,const float* __restrict__ qva,
    const float* __restrict__ vW,const float* __restrict__ vb,const float* __restrict__ vg,
    const float* __restrict__ vbe,const float* __restrict__ vmu,const float* __restrict__ vva)
{
    int c = blockIdx.x, o = threadIdx.x;
    const float *W,*bb,*gg,*be,*mu,*va; int oo;
    if (o < 64)       { W=qW;bb=qb;gg=qg;be=qbe;mu=qmu;va=qva;oo=o; }
    else if (o < 128) { W=kW;bb=kb;gg=kg;be=kbe;mu=kmu;va=kva;oo=o-64; }
    else              { W=vW;bb=vb;gg=vg;be=vbe;mu=vmu;va=vva;oo=o-128; }
    float inv = gg[oo]*rsqrtf(va[oo]+1e-5f);
    g_Wt[c*OCH+o] = W[oo*C_+c]*inv;
    if (c == 0) g_bf[o] = (bb[oo]-mu[oo])*inv + be[oo];
}

// ---------------------------------------------------------------------------
// QKV projection: 128t x 64o tile, 256 thr, 8x4 per thread, FFMA2.
// ---------------------------------------------------------------------------
__global__ __launch_bounds__(256,4) void proj_k(const float* __restrict__ x)
{
    const int t0 = blockIdx.x*128, o0 = blockIdx.y*64, b = blockIdx.z;
    __shared__ float As[32*128], Bs[32*64];
    const int tid = threadIdx.x, mg = tid>>4, ng = tid&15;
    u64t acc[4][4];
    #pragma unroll
    for (int i=0;i<4;i++){ acc[i][0]=0ull;acc[i][1]=0ull;acc[i][2]=0ull;acc[i][3]=0ull; }

    for (int kc = 0; kc < C_; kc += 32) {
        __syncthreads();
        #pragma unroll
        for (int i=0;i<4;i++){
            int f = tid+i*256, kk = f>>5, m4 = f&31;
            *(float4*)&As[kk*128+m4*4] = *(const float4*)&x[((size_t)b*C_+kc+kk)*T_+t0+m4*4];
        }
        #pragma unroll
        for (int i=0;i<2;i++){
            int f = tid+i*256, kk = f>>4, n4 = f&15;
            *(float4*)&Bs[kk*64+n4*4] = *(const float4*)&g_Wt[(kc+kk)*OCH+o0+n4*4];
        }
        __syncthreads();
        #pragma unroll 4
        for (int kk=0;kk<32;kk++){
            float4 aA = *(const float4*)&As[kk*128+mg*8];
            float4 aB = *(const float4*)&As[kk*128+mg*8+4];
            ulonglong2 a0 = *(ulonglong2*)&aA, a1 = *(ulonglong2*)&aB;
            float4 bq = *(const float4*)&Bs[kk*64+ng*4];
            u64t b0=dup2(bq.x),b1=dup2(bq.y),b2=dup2(bq.z),b3=dup2(bq.w);
            u64t av[4] = {a0.x,a0.y,a1.x,a1.y};
            #pragma unroll
            for (int i=0;i<4;i++){
                fma2(acc[i][0],av[i],b0); fma2(acc[i][1],av[i],b1);
                fma2(acc[i][2],av[i],b2); fma2(acc[i][3],av[i],b3);
            }
        }
    }
    float bias[4];
    #pragma unroll
    for (int j=0;j<4;j++) bias[j] = g_bf[o0+ng*4+j];
    #pragma unroll
    for (int i=0;i<4;i++){
        float lo[4],hi[4];
        #pragma unroll
        for (int j=0;j<4;j++) unpk(acc[i][j],lo[j],hi[j]);
        int m = mg*8 + 2*i;
        float4 v;
        v.x=fmaxf(lo[0]+bias[0],0.f); v.y=fmaxf(lo[1]+bias[1],0.f);
        v.z=fmaxf(lo[2]+bias[2],0.f); v.w=fmaxf(lo[3]+bias[3],0.f);
        *(float4*)&g_qkv[((size_t)b*T_+t0+m)*OCH + o0 + ng*4] = v;
        v.x=fmaxf(hi[0]+bias[0],0.f); v.y=fmaxf(hi[1]+bias[1],0.f);
        v.z=fmaxf(hi[2]+bias[2],0.f); v.w=fmaxf(hi[3]+bias[3],0.f);
        *(float4*)&g_qkv[((size_t)b*T_+t0+m+1)*OCH + o0 + ng*4] = v;
    }
}

// ---------------------------------------------------------------------------
// Transpose q/k into [o][t] (q pre-scaled 0.125). grid (64,4,8), 256 thr.
// ---------------------------------------------------------------------------
__global__ __launch_bounds__(256) void trans_k()
{
    __shared__ float ts[32][33];
    const int t0 = blockIdx.x*32, o0 = blockIdx.y*32, b = blockIdx.z;
    {
        int ot = threadIdx.x & 31, tr = threadIdx.x >> 5;
        float sc = (o0 + ot < 64) ? 0.125f : 1.f;
        #pragma unroll
        for (int i=0;i<4;i++){
            int t = tr + i*8;
            ts[ot][t] = g_qkv[((size_t)b*T_ + t0 + t)*OCH + o0 + ot] * sc;
        }
    }
    __syncthreads();
    {
        int tt = threadIdx.x & 31, og = threadIdx.x >> 5;
        #pragma unroll
        for (int i=0;i<4;i++){
            int o = og + i*8;
            g_qkT[((size_t)b*128 + o0 + o)*T_ + t0 + tt] = ts[o][tt];
        }
    }
}

// ---------------------------------------------------------------------------
// Denominator: batch 0, 16-row tiles, grid 128, 256 thr (warp = 2 rows).
// Sub-32 jmin alignment: staged s may reach -31 -> lands in q region of
// g_qkT (in-bounds garbage), masked by jlo >= jmin. Tail tiles stage j up to
// 287 (s <= 2063) -> in-bounds garbage, unread (jhi <= 271 -> s <= 2047).
// ---------------------------------------------------------------------------
__global__ __launch_bounds__(256) void denom_k()
{
    __shared__ float Ss[16*SSTR];
    __shared__ float Qp[64*16];
    __shared__ float Kt[2*64*32];
    const int t0 = blockIdx.x*16;
    const int tid = threadIdx.x, warp = tid>>5, lane = tid&31;
    const int r0 = warp*2;
    const int sbase = t0 - DEPTH_;
    const int jmin = (t0 < DEPTH_) ? DEPTH_ - t0 : 0;
    const float* qT = g_qkT;     // batch 0
    const unsigned qp_u = smem_u32(Qp), kt_u = smem_u32(Kt);

    { int d = tid>>2, c4 = (tid&3)*4;
      cpa16(qp_u + (unsigned)(d*16 + c4)*4u, qT + (size_t)d*T_ + t0 + c4); }
    const int chs = jmin >> 5;
    #pragma unroll
    for (int i=0;i<2;i++){
        int f = tid + i*256, d = f>>3, c4 = (f&7)*4;
        cpa16(kt_u + (unsigned)((chs&1)*2048 + d*32 + c4)*4u,
              qT + (size_t)(64+d)*T_ + sbase + chs*32 + c4);
    }
    CPCOMMIT;

    for (int ch = chs; ch < 9; ch++) {          // jhi <= 271 -> 9 chunks suffice
        CPWAIT0; __syncthreads();
        if (ch + 1 < 9) {
            #pragma unroll
            for (int i=0;i<2;i++){
                int f = tid + i*256, d = f>>3, c4 = (f&7)*4;
                cpa16(kt_u + (unsigned)(((ch+1)&1)*2048 + d*32 + c4)*4u,
                      qT + (size_t)(64+d)*T_ + sbase + (ch+1)*32 + c4);
            }
            CPCOMMIT;
        }
        const float* Kb = Kt + (ch&1)*2048;
        u64t a0 = 0ull;
        #pragma unroll 8
        for (int d = 0; d < 64; d++) {
            u64t qq = *(const u64t*)&Qp[d*16 + r0];   // 2 rows, uniform, 8B aligned
            u64t kk = dup2(Kb[d*32 + lane]);
            fma2(a0, qq, kk);
        }
        float f0,f1; unpk(a0,f0,f1);
        int c = ch*32 + lane;
        Ss[(r0+0)*SSTR+c]=f0; Ss[(r0+1)*SSTR+c]=f1;
    }
    __syncthreads();

    {
        int r = tid>>4, g = tid&15, t = t0 + r;
        int jlo = (r+1 > jmin) ? r+1 : jmin;
        int jhi = r + DEPTH_;
        float mx = 0.f;
        for (int j = jlo + g; j <= jhi; j += 16)
            mx = fmaxf(mx, Ss[r*SSTR + j]);
        mx = fmaxf(mx, __shfl_xor_sync(0xffffffffu, mx, 1));
        mx = fmaxf(mx, __shfl_xor_sync(0xffffffffu, mx, 2));
        mx = fmaxf(mx, __shfl_xor_sync(0xffffffffu, mx, 4));
        mx = fmaxf(mx, __shfl_xor_sync(0xffffffffu, mx, 8));
        float s = 0.f;
        for (int j = jlo + g; j <= jhi; j += 16)
            s += __expf(Ss[r*SSTR + j] - mx);
        s += __shfl_xor_sync(0xffffffffu, s, 1);
        s += __shfl_xor_sync(0xffffffffu, s, 2);
        s += __shfl_xor_sync(0xffffffffu, s, 4);
        s += __shfl_xor_sync(0xffffffffu, s, 8);
        if (g == 0) g_denom[t] = s + 1e-30f;
    }
}

// ---------------------------------------------------------------------------
// Banded attention: 64-row tile, 512 thr, 2 CTA/SM.
// QK: per-warp band-skip of chunks (Ss outside each warp's range is dead:
//     softmax only reads in-window and zero-fills all of [0,320) for PV).
// PV: chunk-local duplicated-P staging (Pd) -> no dup MOVs in inner loop.
// ---------------------------------------------------------------------------
__global__ __launch_bounds__(512,2) void attn_k(const float* __restrict__ x,
                                                float* __restrict__ y)
{
    extern __shared__ float sm[];
    float* Ss = sm;                 // [64][322]
    float* Qp = sm + SS_F;          // [64 d][64 t]
    float* Kt = Qp + 4096;          // [64 d][32 c] single buffer
    float* Vs = sm + SS_F;          // [16 s][256 c] (alias Qp)
    float* Pd = sm + SS_F + 4096;   // [16 jj][128] dup P pairs (alias Kt)

    const int t0 = blockIdx.x*64;
    const int b  = blockIdx.y;
    const int tid = threadIdx.x, warp = tid>>5, lane = tid&31;
    const int r0 = warp*4;
    const int sbase = t0 - DEPTH_;
    const int jmin = (t0 < DEPTH_) ? DEPTH_ - t0 : 0;
    const float* qT = g_qkT + (size_t)b*128*T_;
    const unsigned qp_u = smem_u32(Qp);

    // Q via cp.async (once)
    #pragma unroll
    for (int i=0;i<2;i++){
        int u = tid + i*512, d = u>>4, c4 = u&15;
        cpa16(qp_u + (unsigned)(d*64 + c4*4)*4u, qT + (size_t)d*T_ + t0 + c4*4);
    }
    CPCOMMIT;

    // ---- QK: 32-col chunks, single smem buffer + register prefetch ----
    const int chs = jmin >> 5;
    const int kd = tid>>3, kc4 = (tid&7)*4;
    const int qjA = (r0+1 > jmin) ? r0+1 : jmin;     // warp's first needed j
    const int qjB = r0 + 3 + DEPTH_;                 // warp's last needed j
    float4 kreg = *(const float4*)&qT[(size_t)(64+kd)*T_ + sbase + chs*32 + kc4];
    CPWAIT0;

    for (int ch = chs; ch < 10; ch++) {
        __syncthreads();                             // prev chunk reads done (+Q landed)
        *(float4*)&Kt[kd*32 + kc4] = kreg;
        if (ch + 1 < 10)
            kreg = *(const float4*)&qT[(size_t)(64+kd)*T_ + sbase + (ch+1)*32 + kc4];
        __syncthreads();                             // Kt ready
        if (ch*32 + 31 >= qjA && ch*32 <= qjB) {     // band-skip (warp-uniform)
            u64t a0 = 0ull, a1 = 0ull;
            #pragma unroll 8
            for (int d = 0; d < 64; d++) {
                float4 qf = *(const float4*)&Qp[d*64 + r0]; // warp-uniform bcast
                ulonglong2 qq = *(ulonglong2*)&qf;
                u64t kk = dup2(Kt[d*32 + lane]);
                fma2(a0, qq.x, kk); fma2(a1, qq.y, kk);
            }
            float f0,f1,f2,f3; unpk(a0,f0,f1); unpk(a1,f2,f3);
            int c = ch*32 + lane;
            Ss[(r0+0)*SSTR+c]=f0; Ss[(r0+1)*SSTR+c]=f1;
            Ss[(r0+2)*SSTR+c]=f2; Ss[(r0+3)*SSTR+c]=f3;
        }
    }
    __syncthreads();                 // all scores written; Qp/Kt free

    // prefetch first V chunk to regs (hidden under softmax)
    const int ch16 = jmin >> 4;      // jmin is a multiple of 64
    const int vrow = tid>>6, vc4 = (tid&63)*4;
    float4 vr0 = *(const float4*)&g_qkv[((size_t)b*T_ + sbase + ch16*16 + vrow)*OCH + 128 + vc4];
    float4 vr1 = *(const float4*)&g_qkv[((size_t)b*T_ + sbase + ch16*16 + vrow + 8)*OCH + 128 + vc4];

    // ---- softmax: P = exp(s-max)/denom inside window, 0 outside ----
    {
        int r = tid>>3, g = tid&7, t = t0 + r;
        int jlo = (r+1 > jmin) ? r+1 : jmin;
        int jhi = r + DEPTH_;
        float mx = 0.f;
        for (int j = jlo + g; j <= jhi; j += 8)
            mx = fmaxf(mx, Ss[r*SSTR + j]);
        mx = fmaxf(mx, __shfl_xor_sync(0xffffffffu, mx, 1));
        mx = fmaxf(mx, __shfl_xor_sync(0xffffffffu, mx, 2));
        mx = fmaxf(mx, __shfl_xor_sync(0xffffffffu, mx, 4));
        float invd = 1.f / g_denom[t];
        for (int j = g; j < 320; j += 8) {
            float v = Ss[r*SSTR + j];
            Ss[r*SSTR + j] = (j >= jlo && j <= jhi) ? __expf(v - mx)*invd : 0.f;
        }
    }

    // ---- P @ V: warp = 8 rows x 128 cols; 16-row chunks; dup-P staging ----
    const int rg = warp >> 1, cg = warp & 1;
    const int r0p = rg * 8;
    const int cL = cg*128 + lane*4;
    const int jAw = (r0p+1 > jmin) ? r0p+1 : jmin;
    const int jBw = r0p + 7 + DEPTH_;                // <= 319
    u64t acc[8][2];
    #pragma unroll
    for (int i=0;i<8;i++){ acc[i][0]=0ull; acc[i][1]=0ull; }

    for (int ch = ch16; ch < 20; ch++) {
        __syncthreads();                             // softmax / prev reads done
        int c0 = ch*16;
        *(float4*)&Vs[vrow*256 + vc4]       = vr0;
        *(float4*)&Vs[(vrow+8)*256 + vc4]   = vr1;
        #pragma unroll
        for (int i=0;i<2;i++){                       // stage Pd[jj][2r] = (p,p)
            int u = tid + i*512;                     // 0..1023
            int jj = u >> 6, r = u & 63;
            float p = Ss[r*SSTR + c0 + jj];
            *(float2*)&Pd[jj*128 + 2*r] = make_float2(p, p);
        }
        if (ch + 1 < 20) {
            vr0 = *(const float4*)&g_qkv[((size_t)b*T_ + sbase + (ch+1)*16 + vrow)*OCH + 128 + vc4];
            vr1 = *(const float4*)&g_qkv[((size_t)b*T_ + sbase + (ch+1)*16 + vrow + 8)*OCH + 128 + vc4];
        }
        __syncthreads();                             // Vs + Pd ready
        int bs = (c0 > jAw) ? c0 : jAw;
        int be = (c0+15 < jBw) ? c0+15 : jBw;
        for (int jj = bs; jj <= be; jj++) {
            int lr = jj - c0;
            float4 v0 = *(const float4*)&Vs[lr*256 + cL];
            ulonglong2 vp = *(ulonglong2*)&v0;
            #pragma unroll
            for (int i = 0; i < 8; i++) {
                u64t pd = *(const u64t*)&Pd[lr*128 + 2*(r0p+i)];   // uniform (p,p)
                fma2(acc[i][0], pd, vp.x);
                fma2(acc[i][1], pd, vp.y);
            }
        }
    }

    // ---- epilogue: 8 consecutive t per col -> 2x float4 per col ----
    float o_[8][4];
    #pragma unroll
    for (int i=0;i<8;i++){
        unpk(acc[i][0], o_[i][0], o_[i][1]);
        unpk(acc[i][1], o_[i][2], o_[i][3]);
    }
    #pragma unroll
    for (int k=0;k<4;k++){
        size_t gi = ((size_t)b*C_ + cL + k)*T_ + t0 + r0p;
        float4 xa = *(const float4*)&x[gi];
        float4 o4 = make_float4(xa.x + o_[0][k], xa.y + o_[1][k],
                                xa.z + o_[2][k], xa.w + o_[3][k]);
        *(float4*)&y[gi] = o4;
        float4 xb = *(const float4*)&x[gi + 4];
        float4 o5 = make_float4(xb.x + o_[4][k], xb.y + o_[5][k],
                                xb.z + o_[6][k], xb.w + o_[7][k]);
        *(float4*)&y[gi + 4] = o5;
    }
}

// ---------------------------------------------------------------------------
extern "C" void kernel_launch(void* const* d_in, const int* in_sizes, int n_in,
                              void* d_out, int out_size)
{
    const float* x   = (const float*)d_in[0];
    const float* kW  = (const float*)d_in[1];
    const float* kb  = (const float*)d_in[2];
    const float* kg  = (const float*)d_in[3];
    const float* kbe = (const float*)d_in[4];
    const float* kmu = (const float*)d_in[5];
    const float* kva = (const float*)d_in[6];
    const float* qW  = (const float*)d_in[7];
    const float* qb  = (const float*)d_in[8];
    const float* qg  = (const float*)d_in[9];
    const float* qbe = (const float*)d_in[10];
    const float* qmu = (const float*)d_in[11];
    const float* qva = (const float*)d_in[12];
    const float* vW  = (const float*)d_in[13];
    const float* vb  = (const float*)d_in[14];
    const float* vg  = (const float*)d_in[15];
    const float* vbe = (const float*)d_in[16];
    const float* vmu = (const float*)d_in[17];
    const float* vva = (const float*)d_in[18];
    float* y = (float*)d_out;

    const int smem_attn = SM_F * sizeof(float);      // 107008 B -> 2 CTA/SM
    cudaFuncSetAttribute(attn_k, cudaFuncAttributeMaxDynamicSharedMemorySize, smem_attn);

    fold_k<<<C_, OCH>>>(kW,kb,kg,kbe,kmu,kva, qW,qb,qg,qbe,qmu,qva, vW,vb,vg,vbe,vmu,vva);
    proj_k<<<dim3(T_/128, OCH/64, B_), 256>>>(x);
    trans_k<<<dim3(T_/32, 4, B_), 256>>>();
    denom_k<<<T_/16, 256>>>();
    attn_k<<<dim3(T_/64, B_), 512, smem_attn>>>(x, y);
}

// round 13
// speedup vs baseline: 1.0401x; 1.0401x over previous
#include <cuda_runtime.h>
#include <math.h>

#define B_ 8
#define C_ 256
#define T_ 2048
#define DEPTH_ 256
#define OCH 384
#define SSTR 321                /* 321 % 32 == 1 -> conflict-free column reads */
#define SS_F (64*SSTR)          /* 20544 floats */
#define A_SM_F (SS_F + 6144)    /* + Qp 4096 + Kt 2048 = 26688 fl = 106752 B */
#define PV_SM_F (2*4096 + 2*2048) /* Vd double + Pd double = 12288 fl = 49152 B */

typedef unsigned long long u64t;

__device__ float g_Wt[C_*OCH];
__device__ float g_bf[OCH];
__device__ float g_qkv[B_*T_*OCH];    // [b][t][384]: q|k|v
__device__ float g_qkT[B_*128*T_];    // [b][o][t]: o<64 q*0.125, o>=64 k
__device__ float g_pT[B_*32*320*64];  // [b*32+tile][j][r] transposed probs
__device__ float g_denom[T_];

static __device__ __forceinline__ u64t pk2(float a,float b){u64t r;asm("mov.b64 %0,{%1,%2};":"=l"(r):"f"(a),"f"(b));return r;}
static __device__ __forceinline__ u64t dup2(float a){return pk2(a,a);}
static __device__ __forceinline__ void fma2(u64t&d,u64t a,u64t b){asm("fma.rn.f32x2 %0,%1,%2,%3;":"=l"(d):"l"(a),"l"(b),"l"(d));}
static __device__ __forceinline__ void unpk(u64t v,float&x,float&y){asm("mov.b64 {%0,%1},%2;":"=f"(x),"=f"(y):"l"(v));}
static __device__ __forceinline__ unsigned smem_u32(const void* p){
    unsigned a; asm("{ .reg .u64 t; cvta.to.shared.u64 t, %1; cvt.u32.u64 %0, t; }":"=r"(a):"l"(p)); return a;
}
static __device__ __forceinline__ void cpa16(unsigned dst, const void* src){
    asm volatile("cp.async.cg.shared.global [%0], [%1], 16;" :: "r"(dst), "l"(src));
}
#define CPCOMMIT asm volatile("cp.async.commit_group;" ::: "memory")
#define CPWAIT0  asm volatile("cp.async.wait_group 0;" ::: "memory")
#define CPWAIT1  asm volatile("cp.async.wait_group 1;" ::: "memory")

// ---------------------------------------------------------------------------
__global__ void fold_k(
    const float* __restrict__ kW,const float* __restrict__ kb,const float* __restrict__ kg,
    const float* __restrict__ kbe,const float* __restrict__ kmu,const float* __restrict__ kva,
    const float* __restrict__ qW,const float* __restrict__ qb,const float* __restrict__ qg,
    const float* __restrict__ qbe,const float* __restrict__ qmu,const float* __restrict__ qva,
    const float* __restrict__ vW,const float* __restrict__ vb,const float* __restrict__ vg,
    const float* __restrict__ vbe,const float* __restrict__ vmu,const float* __restrict__ vva)
{
    int c = blockIdx.x, o = threadIdx.x;
    const float *W,*bb,*gg,*be,*mu,*va; int oo;
    if (o < 64)       { W=qW;bb=qb;gg=qg;be=qbe;mu=qmu;va=qva;oo=o; }
    else if (o < 128) { W=kW;bb=kb;gg=kg;be=kbe;mu=kmu;va=kva;oo=o-64; }
    else              { W=vW;bb=vb;gg=vg;be=vbe;mu=vmu;va=vva;oo=o-128; }
    float inv = gg[oo]*rsqrtf(va[oo]+1e-5f);
    g_Wt[c*OCH+o] = W[oo*C_+c]*inv;
    if (c == 0) g_bf[o] = (bb[oo]-mu[oo])*inv + be[oo];
}

// ---------------------------------------------------------------------------
// QKV projection: 128t x 64o tile, 256 thr, 8x4 per thread, FFMA2.
// ---------------------------------------------------------------------------
__global__ __launch_bounds__(256,4) void proj_k(const float* __restrict__ x)
{
    const int t0 = blockIdx.x*128, o0 = blockIdx.y*64, b = blockIdx.z;
    __shared__ float As[32*128], Bs[32*64];
    const int tid = threadIdx.x, mg = tid>>4, ng = tid&15;
    u64t acc[4][4];
    #pragma unroll
    for (int i=0;i<4;i++){ acc[i][0]=0ull;acc[i][1]=0ull;acc[i][2]=0ull;acc[i][3]=0ull; }

    for (int kc = 0; kc < C_; kc += 32) {
        __syncthreads();
        #pragma unroll
        for (int i=0;i<4;i++){
            int f = tid+i*256, kk = f>>5, m4 = f&31;
            *(float4*)&As[kk*128+m4*4] = *(const float4*)&x[((size_t)b*C_+kc+kk)*T_+t0+m4*4];
        }
        #pragma unroll
        for (int i=0;i<2;i++){
            int f = tid+i*256, kk = f>>4, n4 = f&15;
            *(float4*)&Bs[kk*64+n4*4] = *(const float4*)&g_Wt[(kc+kk)*OCH+o0+n4*4];
        }
        __syncthreads();
        #pragma unroll 4
        for (int kk=0;kk<32;kk++){
            float4 aA = *(const float4*)&As[kk*128+mg*8];
            float4 aB = *(const float4*)&As[kk*128+mg*8+4];
            ulonglong2 a0 = *(ulonglong2*)&aA, a1 = *(ulonglong2*)&aB;
            float4 bq = *(const float4*)&Bs[kk*64+ng*4];
            u64t b0=dup2(bq.x),b1=dup2(bq.y),b2=dup2(bq.z),b3=dup2(bq.w);
            u64t av[4] = {a0.x,a0.y,a1.x,a1.y};
            #pragma unroll
            for (int i=0;i<4;i++){
                fma2(acc[i][0],av[i],b0); fma2(acc[i][1],av[i],b1);
                fma2(acc[i][2],av[i],b2); fma2(acc[i][3],av[i],b3);
            }
        }
    }
    float bias[4];
    #pragma unroll
    for (int j=0;j<4;j++) bias[j] = g_bf[o0+ng*4+j];
    #pragma unroll
    for (int i=0;i<4;i++){
        float lo[4],hi[4];
        #pragma unroll
        for (int j=0;j<4;j++) unpk(acc[i][j],lo[j],hi[j]);
        int m = mg*8 + 2*i;
        float4 v;
        v.x=fmaxf(lo[0]+bias[0],0.f); v.y=fmaxf(lo[1]+bias[1],0.f);
        v.z=fmaxf(lo[2]+bias[2],0.f); v.w=fmaxf(lo[3]+bias[3],0.f);
        *(float4*)&g_qkv[((size_t)b*T_+t0+m)*OCH + o0 + ng*4] = v;
        v.x=fmaxf(hi[0]+bias[0],0.f); v.y=fmaxf(hi[1]+bias[1],0.f);
        v.z=fmaxf(hi[2]+bias[2],0.f); v.w=fmaxf(hi[3]+bias[3],0.f);
        *(float4*)&g_qkv[((size_t)b*T_+t0+m+1)*OCH + o0 + ng*4] = v;
    }
}

// ---------------------------------------------------------------------------
// Transpose q/k into [o][t] (q pre-scaled 0.125). grid (64,4,8), 256 thr.
// ---------------------------------------------------------------------------
__global__ __launch_bounds__(256) void trans_k()
{
    __shared__ float ts[32][33];
    const int t0 = blockIdx.x*32, o0 = blockIdx.y*32, b = blockIdx.z;
    {
        int ot = threadIdx.x & 31, tr = threadIdx.x >> 5;
        float sc = (o0 + ot < 64) ? 0.125f : 1.f;
        #pragma unroll
        for (int i=0;i<4;i++){
            int t = tr + i*8;
            ts[ot][t] = g_qkv[((size_t)b*T_ + t0 + t)*OCH + o0 + ot] * sc;
        }
    }
    __syncthreads();
    {
        int tt = threadIdx.x & 31, og = threadIdx.x >> 5;
        #pragma unroll
        for (int i=0;i<4;i++){
            int o = og + i*8;
            g_qkT[((size_t)b*128 + o0 + o)*T_ + t0 + tt] = ts[o][tt];
        }
    }
}

// ---------------------------------------------------------------------------
// Denominator: batch 0, 16-row tiles, grid 128, 256 thr (warp = 2 rows).
// ---------------------------------------------------------------------------
__global__ __launch_bounds__(256) void denom_k()
{
    __shared__ float Ss[16*SSTR];
    __shared__ float Qp[64*16];
    __shared__ float Kt[2*64*32];
    const int t0 = blockIdx.x*16;
    const int tid = threadIdx.x, warp = tid>>5, lane = tid&31;
    const int r0 = warp*2;
    const int sbase = t0 - DEPTH_;
    const int jmin = (t0 < DEPTH_) ? DEPTH_ - t0 : 0;
    const float* qT = g_qkT;     // batch 0
    const unsigned qp_u = smem_u32(Qp), kt_u = smem_u32(Kt);

    { int d = tid>>2, c4 = (tid&3)*4;
      cpa16(qp_u + (unsigned)(d*16 + c4)*4u, qT + (size_t)d*T_ + t0 + c4); }
    const int chs = jmin >> 5;
    #pragma unroll
    for (int i=0;i<2;i++){
        int f = tid + i*256, d = f>>3, c4 = (f&7)*4;
        cpa16(kt_u + (unsigned)((chs&1)*2048 + d*32 + c4)*4u,
              qT + (size_t)(64+d)*T_ + sbase + chs*32 + c4);
    }
    CPCOMMIT;

    for (int ch = chs; ch < 9; ch++) {
        CPWAIT0; __syncthreads();
        if (ch + 1 < 9) {
            #pragma unroll
            for (int i=0;i<2;i++){
                int f = tid + i*256, d = f>>3, c4 = (f&7)*4;
                cpa16(kt_u + (unsigned)(((ch+1)&1)*2048 + d*32 + c4)*4u,
                      qT + (size_t)(64+d)*T_ + sbase + (ch+1)*32 + c4);
            }
            CPCOMMIT;
        }
        const float* Kb = Kt + (ch&1)*2048;
        u64t a0 = 0ull;
        #pragma unroll 8
        for (int d = 0; d < 64; d++) {
            u64t qq = *(const u64t*)&Qp[d*16 + r0];
            u64t kk = dup2(Kb[d*32 + lane]);
            fma2(a0, qq, kk);
        }
        float f0,f1; unpk(a0,f0,f1);
        int c = ch*32 + lane;
        Ss[(r0+0)*SSTR+c]=f0; Ss[(r0+1)*SSTR+c]=f1;
    }
    __syncthreads();

    {
        int r = tid>>4, g = tid&15, t = t0 + r;
        int jlo = (r+1 > jmin) ? r+1 : jmin;
        int jhi = r + DEPTH_;
        float mx = 0.f;
        for (int j = jlo + g; j <= jhi; j += 16)
            mx = fmaxf(mx, Ss[r*SSTR + j]);
        mx = fmaxf(mx, __shfl_xor_sync(0xffffffffu, mx, 1));
        mx = fmaxf(mx, __shfl_xor_sync(0xffffffffu, mx, 2));
        mx = fmaxf(mx, __shfl_xor_sync(0xffffffffu, mx, 4));
        mx = fmaxf(mx, __shfl_xor_sync(0xffffffffu, mx, 8));
        float s = 0.f;
        for (int j = jlo + g; j <= jhi; j += 16)
            s += __expf(Ss[r*SSTR + j] - mx);
        s += __shfl_xor_sync(0xffffffffu, s, 1);
        s += __shfl_xor_sync(0xffffffffu, s, 2);
        s += __shfl_xor_sync(0xffffffffu, s, 4);
        s += __shfl_xor_sync(0xffffffffu, s, 8);
        if (g == 0) g_denom[t] = s + 1e-30f;
    }
}

// ---------------------------------------------------------------------------
// QK + softmax: 64-row tile, 512 thr, 2 CTA/SM. Writes P transposed to g_pT.
// ---------------------------------------------------------------------------
__global__ __launch_bounds__(512,2) void qksoft_k()
{
    extern __shared__ float sm[];
    float* Ss = sm;                 // [64][321]
    float* Qp = sm + SS_F;          // [64 d][64 t]
    float* Kt = Qp + 4096;          // [64 d][32 c]

    const int t0 = blockIdx.x*64;
    const int b  = blockIdx.y;
    const int tid = threadIdx.x, warp = tid>>5, lane = tid&31;
    const int r0 = warp*4;
    const int sbase = t0 - DEPTH_;
    const int jmin = (t0 < DEPTH_) ? DEPTH_ - t0 : 0;
    const float* qT = g_qkT + (size_t)b*128*T_;
    const unsigned qp_u = smem_u32(Qp);

    #pragma unroll
    for (int i=0;i<2;i++){
        int u = tid + i*512, d = u>>4, c4 = u&15;
        cpa16(qp_u + (unsigned)(d*64 + c4*4)*4u, qT + (size_t)d*T_ + t0 + c4*4);
    }
    CPCOMMIT;

    const int chs = jmin >> 5;
    const int kd = tid>>3, kc4 = (tid&7)*4;
    float4 kreg = *(const float4*)&qT[(size_t)(64+kd)*T_ + sbase + chs*32 + kc4];
    CPWAIT0;

    for (int ch = chs; ch < 10; ch++) {
        __syncthreads();
        *(float4*)&Kt[kd*32 + kc4] = kreg;
        if (ch + 1 < 10)
            kreg = *(const float4*)&qT[(size_t)(64+kd)*T_ + sbase + (ch+1)*32 + kc4];
        __syncthreads();
        u64t a0 = 0ull, a1 = 0ull;
        #pragma unroll 8
        for (int d = 0; d < 64; d++) {
            float4 qf = *(const float4*)&Qp[d*64 + r0];   // warp-uniform bcast
            ulonglong2 qq = *(ulonglong2*)&qf;
            u64t kk = dup2(Kt[d*32 + lane]);
            fma2(a0, qq.x, kk); fma2(a1, qq.y, kk);
        }
        float f0,f1,f2,f3; unpk(a0,f0,f1); unpk(a1,f2,f3);
        int c = ch*32 + lane;
        Ss[(r0+0)*SSTR+c]=f0; Ss[(r0+1)*SSTR+c]=f1;
        Ss[(r0+2)*SSTR+c]=f2; Ss[(r0+3)*SSTR+c]=f3;
    }
    __syncthreads();

    // softmax: P = exp(s-max)/denom inside window, 0 outside (all [0,320))
    {
        int r = tid>>3, g = tid&7, t = t0 + r;
        int jlo = (r+1 > jmin) ? r+1 : jmin;
        int jhi = r + DEPTH_;
        float mx = 0.f;
        for (int j = jlo + g; j <= jhi; j += 8)
            mx = fmaxf(mx, Ss[r*SSTR + j]);
        mx = fmaxf(mx, __shfl_xor_sync(0xffffffffu, mx, 1));
        mx = fmaxf(mx, __shfl_xor_sync(0xffffffffu, mx, 2));
        mx = fmaxf(mx, __shfl_xor_sync(0xffffffffu, mx, 4));
        float invd = 1.f / g_denom[t];
        for (int j = g; j < 320; j += 8) {
            float v = Ss[r*SSTR + j];
            Ss[r*SSTR + j] = (j >= jlo && j <= jhi) ? __expf(v - mx)*invd : 0.f;
        }
    }
    __syncthreads();

    // transposed write: g_pT[bt][j][r], conflict-free Ss reads (321%32==1)
    {
        float* dst = g_pT + (size_t)(b*32 + blockIdx.x)*(320*64);
        int r = tid & 63, jg = tid >> 6;
        #pragma unroll 4
        for (int k2 = 0; k2 < 40; k2++){
            int j = jg*40 + k2;
            dst[(size_t)j*64 + r] = Ss[r*SSTR + j];
        }
    }
}

// ---------------------------------------------------------------------------
// P @ V: 64-row tile, 512 thr, 2 CTA/SM. Double-buffered cp.async V +
// double-buffered duplicated-P (Pd[j][2r]=(p,p)) -> fma-bound inner loop.
// ---------------------------------------------------------------------------
__global__ __launch_bounds__(512,2) void pv_k(const float* __restrict__ x,
                                              float* __restrict__ y)
{
    extern __shared__ float psm[];
    float* Vd = psm;            // 2 x [16 s][256 c]
    float* Pd = psm + 8192;     // 2 x [16 j][128]  (p,p) pairs

    const int tile = blockIdx.x, b = blockIdx.y, t0 = tile*64;
    const int tid = threadIdx.x, warp = tid>>5, lane = tid&31;
    const int sbase = t0 - DEPTH_;
    const int jmin = (t0 < DEPTH_) ? DEPTH_ - t0 : 0;
    const int ch0 = jmin >> 4;           // jmin multiple of 64
    const int rg = warp>>1, cg = warp&1, r0p = rg*8;
    const int cL = cg*128 + lane*4;
    const int jAw = (r0p+1 > jmin) ? r0p+1 : jmin;
    const int jBw = r0p + 7 + DEPTH_;    // <= 319
    const float* pT = g_pT + (size_t)(b*32 + tile)*(320*64);
    const int vrow = tid>>6, vc4 = (tid&63)*4;
    const int pj = tid>>6, pr = tid&63;
    const unsigned vd_u = smem_u32(Vd);

    // prefetch chunk ch0 (V via cp.async, P via LDG)
    cpa16(vd_u + (unsigned)((ch0&1)*4096 + vrow*256 + vc4)*4u,
          &g_qkv[((size_t)b*T_ + sbase + ch0*16 + vrow)*OCH + 128 + vc4]);
    cpa16(vd_u + (unsigned)((ch0&1)*4096 + (vrow+8)*256 + vc4)*4u,
          &g_qkv[((size_t)b*T_ + sbase + ch0*16 + vrow + 8)*OCH + 128 + vc4]);
    CPCOMMIT;
    float pA = pT[(size_t)(ch0*16 + pj)*64 + pr];
    float pB = pT[(size_t)(ch0*16 + pj + 8)*64 + pr];

    u64t acc[8][2];
    #pragma unroll
    for (int i=0;i<8;i++){ acc[i][0]=0ull; acc[i][1]=0ull; }

    for (int ch = ch0; ch < 20; ch++) {
        __syncthreads();                 // readers of buf[(ch+1)&1] done
        float* Pb = Pd + (ch&1)*2048;
        *(float2*)&Pb[pj*128 + 2*pr]     = make_float2(pA, pA);
        *(float2*)&Pb[(pj+8)*128 + 2*pr] = make_float2(pB, pB);
        if (ch + 1 < 20) {
            cpa16(vd_u + (unsigned)(((ch+1)&1)*4096 + vrow*256 + vc4)*4u,
                  &g_qkv[((size_t)b*T_ + sbase + (ch+1)*16 + vrow)*OCH + 128 + vc4]);
            cpa16(vd_u + (unsigned)(((ch+1)&1)*4096 + (vrow+8)*256 + vc4)*4u,
                  &g_qkv[((size_t)b*T_ + sbase + (ch+1)*16 + vrow + 8)*OCH + 128 + vc4]);
            CPCOMMIT;
            pA = pT[(size_t)((ch+1)*16 + pj)*64 + pr];
            pB = pT[(size_t)((ch+1)*16 + pj + 8)*64 + pr];
            CPWAIT1;                     // V(ch) landed; V(ch+1) may fly
        } else {
            CPWAIT0;
        }
        __syncthreads();                 // Vd(ch) + Pd(ch) visible
        const float* Vb = Vd + (ch&1)*4096;
        int c0 = ch*16;
        int bs = (c0 > jAw) ? c0 : jAw;
        int be = (c0+15 < jBw) ? c0+15 : jBw;
        for (int jj = bs; jj <= be; jj++) {
            int lr = jj - c0;
            float4 v0 = *(const float4*)&Vb[lr*256 + cL];
            ulonglong2 vp = *(ulonglong2*)&v0;
            #pragma unroll
            for (int i = 0; i < 8; i++) {
                u64t pd = *(const u64t*)&Pb[lr*128 + 2*(r0p+i)];   // uniform (p,p)
                fma2(acc[i][0], pd, vp.x);
                fma2(acc[i][1], pd, vp.y);
            }
        }
    }

    // epilogue: 8 consecutive t per col -> 2x float4 per col
    float o_[8][4];
    #pragma unroll
    for (int i=0;i<8;i++){
        unpk(acc[i][0], o_[i][0], o_[i][1]);
        unpk(acc[i][1], o_[i][2], o_[i][3]);
    }
    #pragma unroll
    for (int k=0;k<4;k++){
        size_t gi = ((size_t)b*C_ + cL + k)*T_ + t0 + r0p;
        float4 xa = *(const float4*)&x[gi];
        float4 o4 = make_float4(xa.x + o_[0][k], xa.y + o_[1][k],
                                xa.z + o_[2][k], xa.w + o_[3][k]);
        *(float4*)&y[gi] = o4;
        float4 xb = *(const float4*)&x[gi + 4];
        float4 o5 = make_float4(xb.x + o_[4][k], xb.y + o_[5][k],
                                xb.z + o_[6][k], xb.w + o_[7][k]);
        *(float4*)&y[gi + 4] = o5;
    }
}

// ---------------------------------------------------------------------------
extern "C" void kernel_launch(void* const* d_in, const int* in_sizes, int n_in,
                              void* d_out, int out_size)
{
    const float* x   = (const float*)d_in[0];
    const float* kW  = (const float*)d_in[1];
    const float* kb  = (const float*)d_in[2];
    const float* kg  = (const float*)d_in[3];
    const float* kbe = (const float*)d_in[4];
    const float* kmu = (const float*)d_in[5];
    const float* kva = (const float*)d_in[6];
    const float* qW  = (const float*)d_in[7];
    const float* qb  = (const float*)d_in[8];
    const float* qg  = (const float*)d_in[9];
    const float* qbe = (const float*)d_in[10];
    const float* qmu = (const float*)d_in[11];
    const float* qva = (const float*)d_in[12];
    const float* vW  = (const float*)d_in[13];
    const float* vb  = (const float*)d_in[14];
    const float* vg  = (const float*)d_in[15];
    const float* vbe = (const float*)d_in[16];
    const float* vmu = (const float*)d_in[17];
    const float* vva = (const float*)d_in[18];
    float* y = (float*)d_out;

    const int smem_a  = A_SM_F  * sizeof(float);   // 106752 B
    const int smem_pv = PV_SM_F * sizeof(float);   // 49152 B
    cudaFuncSetAttribute(qksoft_k, cudaFuncAttributeMaxDynamicSharedMemorySize, smem_a);
    cudaFuncSetAttribute(pv_k,     cudaFuncAttributeMaxDynamicSharedMemorySize, smem_pv);

    fold_k<<<C_, OCH>>>(kW,kb,kg,kbe,kmu,kva, qW,qb,qg,qbe,qmu,qva, vW,vb,vg,vbe,vmu,vva);
    proj_k<<<dim3(T_/128, OCH/64, B_), 256>>>(x);
    trans_k<<<dim3(T_/32, 4, B_), 256>>>();
    denom_k<<<T_/16, 256>>>();
    qksoft_k<<<dim3(T_/64, B_), 512, smem_a>>>();
    pv_k<<<dim3(T_/64, B_), 512, smem_pv>>>(x, y);
}